// round 7
// baseline (speedup 1.0000x reference)
#include <cuda_runtime.h>

#define BATCH 8
#define NPT   65536
#define TOT   (BATCH*NPT)
#define CIN   16
#define SENTV 2000000000
#define LUTB  2146689          // 129^3
#define NBLK  525              // scan blocks per batch (525*4096 >= LUTB)
#define LUTS  (NBLK*4096)      // padded per-batch LUT stride = 2150400
#define NBLKTOT (BATCH*NBLK)   // 4200
#define PPB   512

__device__ unsigned d_code[TOT];                 // per-point compact voxel code
__device__ unsigned char d_pres[BATCH*(size_t)LUTS];   // presence bytes (maintained-zero)
__device__ int d_lut[BATCH*(size_t)LUTS];        // rank+1 at present entries (maintained-zero)
__device__ int d_blocksum[NBLKTOT];
__device__ int d_blockoff[NBLKTOT];
__device__ int d_batchtot[BATCH];
__device__ int d_unq[TOT];                       // slot -> compact code (SENTV if invalid)
__device__ int d_invmap[TOT];
__device__ float d_vfeat[TOT*CIN];
__device__ float d_cnt[TOT];
__device__ unsigned long long d_pairs[27u*TOT];
__device__ unsigned d_paircnt[27];
__device__ unsigned d_chunkpfx[28];
__device__ unsigned d_totchunks;
__device__ int d_validcount;
__device__ unsigned d_originbits[3];
__device__ float d_h1[TOT*32];
__device__ float d_h2[TOT*64];
__device__ float d_h3[(size_t)TOT*128];
__device__ double d_sumv[3][128];
__device__ double d_sumsq[3][128];
__device__ float d_bnmean[3][128];
__device__ float d_bnrstd[3][128];

// ---------- helpers ----------
__device__ __forceinline__ unsigned f2ord(float f){
    unsigned u=__float_as_uint(f);
    return (u&0x80000000u)? ~u : (u|0x80000000u);
}
__device__ __forceinline__ float ord2f(unsigned u){
    return (u&0x80000000u)? __uint_as_float(u^0x80000000u) : __uint_as_float(~u);
}
__device__ __forceinline__ unsigned long long pk2(float a,float b){
    unsigned long long r;
    asm("mov.b64 %0,{%1,%2};":"=l"(r):"f"(a),"f"(b));
    return r;
}
__device__ __forceinline__ unsigned long long dup2(float a){
    unsigned long long r;
    asm("mov.b64 %0,{%1,%1};":"=l"(r):"f"(a));
    return r;
}
__device__ __forceinline__ unsigned long long ffma2(unsigned long long a,unsigned long long b,unsigned long long c){
    unsigned long long d;
    asm("fma.rn.f32x2 %0,%1,%2,%3;":"=l"(d):"l"(a),"l"(b),"l"(c));
    return d;
}
__device__ __forceinline__ void upk2(unsigned long long v,float&a,float&b){
    asm("mov.b64 {%0,%1},%2;":"=f"(a),"=f"(b):"l"(v));
}
__device__ __forceinline__ void red4(float* addr,float a,float b,float c,float d){
    asm volatile("red.global.add.v4.f32 [%0],{%1,%2,%3,%4};"
        ::"l"(addr),"f"(a),"f"(b),"f"(c),"f"(d):"memory");
}
__device__ __forceinline__ void red2(float* addr,float a,float b){
    asm volatile("red.global.add.v2.f32 [%0],{%1,%2};"
        ::"l"(addr),"f"(a),"f"(b):"memory");
}
__device__ __forceinline__ void red1(float* addr,float a){
    asm volatile("red.global.add.f32 [%0],%1;"
        ::"l"(addr),"f"(a):"memory");
}

// ---------- init: clear per-launch state (LUT/presence are maintained-zero) ----------
__global__ void k_init(){
    int stride=gridDim.x*blockDim.x;
    for(int t=blockIdx.x*blockDim.x+threadIdx.x;t<TOT;t+=stride){
        d_unq[t]=SENTV;
        d_cnt[t]=0.f;
        float4 z=make_float4(0,0,0,0);
        float4* vp=(float4*)&d_vfeat[(size_t)t*CIN];
        vp[0]=z; vp[1]=z; vp[2]=z; vp[3]=z;
        if(t<27)  d_paircnt[t]=0u;
        if(t<3)   d_originbits[t]=0xFFFFFFFFu;
        if(t<384){ ((double*)d_sumv)[t]=0.0; ((double*)d_sumsq)[t]=0.0; }
        if(t==0)  d_validcount=0;
    }
}

// ---------- per-dim min ----------
__global__ void k_min(const float* __restrict__ xyz){
    __shared__ unsigned sm0[8],sm1[8],sm2[8];
    unsigned m0=0xFFFFFFFFu,m1=0xFFFFFFFFu,m2=0xFFFFFFFFu;
    int stride=gridDim.x*blockDim.x;
    for(int p=blockIdx.x*blockDim.x+threadIdx.x;p<TOT;p+=stride){
        m0=min(m0,f2ord(xyz[3*p+0]));
        m1=min(m1,f2ord(xyz[3*p+1]));
        m2=min(m2,f2ord(xyz[3*p+2]));
    }
    m0=__reduce_min_sync(0xffffffffu,m0);
    m1=__reduce_min_sync(0xffffffffu,m1);
    m2=__reduce_min_sync(0xffffffffu,m2);
    int w=threadIdx.x>>5;
    if((threadIdx.x&31)==0){ sm0[w]=m0; sm1[w]=m1; sm2[w]=m2; }
    __syncthreads();
    if(threadIdx.x==0){
        for(int k=1;k<(int)(blockDim.x>>5);k++){
            m0=min(m0,sm0[k]); m1=min(m1,sm1[k]); m2=min(m2,sm2[k]);
        }
        atomicMin(&d_originbits[0],m0);
        atomicMin(&d_originbits[1],m1);
        atomicMin(&d_originbits[2],m2);
    }
}

// ---------- mark: per-point compact code + presence byte ----------
__global__ void k_mark(const float* __restrict__ xyz){
    float o0=ord2f(d_originbits[0]);
    float o1=ord2f(d_originbits[1]);
    float o2=ord2f(d_originbits[2]);
    int stride=gridDim.x*blockDim.x;
    for(int p=blockIdx.x*blockDim.x+threadIdx.x;p<TOT;p+=stride){
        int v0=(int)__fdiv_rn(xyz[3*p+0]-o0,0.4f); if(v0<0)v0=0;
        int v1=(int)__fdiv_rn(xyz[3*p+1]-o1,0.4f); if(v1<0)v1=0;
        int v2=(int)__fdiv_rn(xyz[3*p+2]-o2,0.4f); if(v2<0)v2=0;
        unsigned cidx=(unsigned)((v2*129+v1)*129+v0);   // order-isomorphic to base-1000 lin
        d_code[p]=cidx;
        d_pres[(size_t)(p>>16)*LUTS+cidx]=1;
    }
}

// ---------- scan A: per-block presence sums (4096 bytes/block) ----------
__global__ void k_scanA(){
    int tid=threadIdx.x;
    size_t base=(size_t)blockIdx.x*4096+(size_t)tid*16;
    uint4 a=*(const uint4*)&d_pres[base];
    int s=__popc(a.x)+__popc(a.y)+__popc(a.z)+__popc(a.w); // bytes are 0/1
    __shared__ int sm[8];
    s=__reduce_add_sync(0xffffffffu,s);
    if((tid&31)==0) sm[tid>>5]=s;
    __syncthreads();
    if(tid==0){
        int t=0;
        #pragma unroll
        for(int k=0;k<8;k++) t+=sm[k];
        d_blocksum[blockIdx.x]=t;
    }
}

// ---------- scan B: per-batch serial scan of 525 block sums ----------
__global__ void k_scanB(){
    int b=threadIdx.x;
    if(b<BATCH){
        int off=0;
        for(int j=0;j<NBLK;j++){
            d_blockoff[b*NBLK+j]=off;
            off+=d_blocksum[b*NBLK+j];
        }
        d_batchtot[b]=off;
    }
}

// ---------- scan C: write LUT=rank+1 and unq[slot]=code at present entries ----------
__global__ void k_scanC(){
    int tid=threadIdx.x;
    int bid=blockIdx.x;
    int batch=bid/NBLK, jb=bid%NBLK;
    size_t base=(size_t)bid*4096+(size_t)tid*16;
    uint4 a=*(const uint4*)&d_pres[base];
    int s=__popc(a.x)+__popc(a.y)+__popc(a.z)+__popc(a.w);
    // block exclusive prefix over thread sums
    __shared__ int sm[256];
    sm[tid]=s; __syncthreads();
    #pragma unroll
    for(int off=1;off<256;off<<=1){
        int t=(tid>=off)?sm[tid-off]:0;
        __syncthreads();
        sm[tid]+=t;
        __syncthreads();
    }
    int run=d_blockoff[bid]+sm[tid]-s;
    if(s){
        unsigned char by[16];
        *(uint4*)by=a;
        int cbase=jb*4096+tid*16;
        #pragma unroll
        for(int k=0;k<16;k++){
            if(by[k]){
                int cidx=cbase+k;
                d_lut[(size_t)batch*LUTS+cidx]=run+1;
                d_unq[(batch<<16)+run]=cidx;
                run++;
            }
        }
    }
}

// ---------- build: invmap + voxel-mean accumulation via RED ----------
__global__ void k_build2(const float* __restrict__ feat, const float* __restrict__ mask){
    int stride=gridDim.x*blockDim.x;
    for(int p=blockIdx.x*blockDim.x+threadIdx.x;p<TOT;p+=stride){
        int b=p>>16;
        unsigned cidx=d_code[p];
        int rank=d_lut[(size_t)b*LUTS+cidx]-1;
        d_invmap[p]=rank;
        float m=mask[p];
        if(m!=0.f){
            int slot=(b<<16)+rank;
            const float4* fp=(const float4*)&feat[(size_t)p*CIN];
            float4 f0=fp[0],f1=fp[1],f2=fp[2],f3=fp[3];
            float* vp=&d_vfeat[(size_t)slot*CIN];
            red4(vp+0 ,f0.x*m,f0.y*m,f0.z*m,f0.w*m);
            red4(vp+4 ,f1.x*m,f1.y*m,f1.z*m,f1.w*m);
            red4(vp+8 ,f2.x*m,f2.y*m,f2.z*m,f2.w*m);
            red4(vp+12,f3.x*m,f3.y*m,f3.z*m,f3.w*m);
            red1(&d_cnt[slot],m);
        }
    }
}

// ---------- divide voxel sums by counts ----------
__global__ void k_vdiv(){
    int stride=gridDim.x*blockDim.x;
    for(int slot=blockIdx.x*blockDim.x+threadIdx.x;slot<TOT;slot+=stride){
        if(d_unq[slot]<SENTV){
            float rC=1.0f/fmaxf(d_cnt[slot],1.f);
            float4* vp=(float4*)&d_vfeat[(size_t)slot*CIN];
            #pragma unroll
            for(int k=0;k<4;k++){
                float4 v=vp[k];
                v.x*=rC; v.y*=rC; v.z*=rC; v.w*=rC;
                vp[k]=v;
            }
        }
    }
}

// ---------- off-center pairs (base-129 arithmetic) ----------
__global__ void k_pairs(){
    int slot=blockIdx.x*blockDim.x+threadIdx.x;
    int lane=threadIdx.x&31;
    int cidx=d_unq[slot];
    bool vv=(cidx<SENTV);
    int b=slot>>16;
    int x=0,y=0,z=0;
    if(vv){ x=cidx%129; int t=cidx/129; y=t%129; z=t/129; }
    #pragma unroll
    for(int ko=0;ko<27;ko++){
        if(ko==13) continue;
        int dx=(ko%3)-1, dy=((ko/3)%3)-1, dz=(ko/9)-1;
        int nx=x+dx, ny=y+dy, nz=z+dz;
        bool inb=vv && nx>=0 && ny>=0 && nz>=0 && nx<=128 && ny<=128 && nz<=128;
        int r=0;
        if(inb) r=d_lut[(size_t)b*LUTS+(cidx+dx+129*dy+16641*dz)];
        bool ok=inb && (r>0);
        unsigned m=__ballot_sync(0xffffffffu,ok);
        unsigned base=0;
        if(lane==0 && m) base=atomicAdd(&d_paircnt[ko],(unsigned)__popc(m));
        base=__shfl_sync(0xffffffffu,base,0);
        if(ok){
            unsigned pos=base+__popc(m&((1u<<lane)-1u));
            d_pairs[(size_t)ko*TOT+pos]=
                ((unsigned long long)(unsigned)slot<<32)|(unsigned)((b<<16)+(r-1));
        }
    }
}

// ---------- restore LUT + presence to zero via touched entries ----------
__global__ void k_unclear(){
    int stride=gridDim.x*blockDim.x;
    for(int slot=blockIdx.x*blockDim.x+threadIdx.x;slot<TOT;slot+=stride){
        int cidx=d_unq[slot];
        if(cidx<SENTV){
            size_t idx=(size_t)(slot>>16)*LUTS+cidx;
            d_lut[idx]=0;
            d_pres[idx]=0;
        }
    }
}

__global__ void k_sched(){
    if(threadIdx.x==0&&blockIdx.x==0){
        int vc=0;
        for(int b=0;b<BATCH;b++) vc+=d_batchtot[b];
        d_validcount=vc;
        unsigned acc=0; d_chunkpfx[0]=0;
        for(int ko=0;ko<27;ko++){
            acc+=(d_paircnt[ko]+PPB-1)/PPB;
            d_chunkpfx[ko+1]=acc;
        }
        d_totchunks=acc;
    }
}

// ---------- hoisted BN params per lane-channel ----------
template<int BNL,int RI,int CI>
__device__ __forceinline__ void bn_hoist(int lane,const float* gam,const float* bet,
        float (&sc)[RI], float (&sh)[RI]){
    #pragma unroll
    for(int j=0;j<RI;j++){
        int c=lane+32*j;
        if constexpr(BNL>=0){
            if(c<CI){
                float a=d_bnrstd[BNL][c]*gam[c];
                sc[j]=a; sh[j]=bet[c]-d_bnmean[BNL][c]*a;
            } else { sc[j]=0.f; sh[j]=0.f; }
        } else { sc[j]=1.f; sh[j]=0.f; }
    }
}
template<int BNL>
__device__ __forceinline__ float bn_apply(float v,float sc,float sh){
    if constexpr(BNL>=0) return fmaxf(fmaf(v,sc,sh),0.f);
    else return v;
}

// ---------- center tap (V=8 voxels per warp for CO>=64, V=4 for CO=32) ----------
template<int CI,int CO,int BNL>
__global__ void k_center(const float* __restrict__ in, float* __restrict__ out,
        const float* __restrict__ W, const float* __restrict__ bias,
        const float* __restrict__ gam, const float* __restrict__ bet){
    constexpr int RI=(CI+31)/32;
    int lane=threadIdx.x&31;
    float sc[RI],sh[RI];
    bn_hoist<BNL,RI,CI>(lane,gam,bet,sc,sh);
    if constexpr (CO==128){
        __shared__ ulonglong2 sW[CI*32];
        for(int i=threadIdx.x;i<CI*32;i+=blockDim.x){
            int ci=i>>5, ln=i&31;
            float4 w=*(const float4*)&W[(size_t)13*CI*CO+(size_t)ci*CO+ln*4];
            sW[i]=make_ulonglong2(pk2(w.x,w.y),pk2(w.z,w.w));
        }
        __syncthreads();
        float4 bs=*(const float4*)&bias[lane*4];
        unsigned long long bias0=pk2(bs.x,bs.y), bias1=pk2(bs.z,bs.w);
        int base0=(((blockIdx.x*blockDim.x+threadIdx.x)>>5)<<3);
        int stride8=((gridDim.x*blockDim.x)>>5)<<3;
        for(int base=base0;base<TOT;base+=stride8){
            bool val[8];
            float r[8][RI];
            #pragma unroll
            for(int v=0;v<8;v++){
                val[v]=(d_unq[base+v]<SENTV);
                #pragma unroll
                for(int j=0;j<RI;j++)
                    r[v][j]=bn_apply<BNL>(in[(size_t)(base+v)*CI+lane+32*j],sc[j],sh[j]);
            }
            unsigned long long a0[8],a1[8];
            #pragma unroll
            for(int v=0;v<8;v++){ a0[v]=bias0; a1[v]=bias1; }
            #pragma unroll
            for(int ci=0;ci<CI;ci++){
                ulonglong2 w=sW[ci*32+lane];
                #pragma unroll
                for(int v=0;v<8;v++){
                    unsigned long long ff=dup2(__shfl_sync(0xffffffffu,r[v][ci>>5],ci&31));
                    a0[v]=ffma2(ff,w.x,a0[v]);
                    a1[v]=ffma2(ff,w.y,a1[v]);
                }
            }
            #pragma unroll
            for(int v=0;v<8;v++) if(val[v]){
                float4 o; upk2(a0[v],o.x,o.y); upk2(a1[v],o.z,o.w);
                *(float4*)&out[(size_t)(base+v)*CO+lane*4]=o;
            }
        }
    } else if constexpr (CO==64){
        __shared__ unsigned long long sW[CI*32];
        for(int i=threadIdx.x;i<CI*32;i+=blockDim.x){
            int ci=i>>5, ln=i&31;
            float2 w=*(const float2*)&W[(size_t)13*CI*CO+(size_t)ci*CO+ln*2];
            sW[i]=pk2(w.x,w.y);
        }
        __syncthreads();
        float2 bs=*(const float2*)&bias[lane*2];
        unsigned long long bias0=pk2(bs.x,bs.y);
        int base0=(((blockIdx.x*blockDim.x+threadIdx.x)>>5)<<3);
        int stride8=((gridDim.x*blockDim.x)>>5)<<3;
        for(int base=base0;base<TOT;base+=stride8){
            bool val[8];
            float r[8];
            #pragma unroll
            for(int v=0;v<8;v++){
                val[v]=(d_unq[base+v]<SENTV);
                r[v]=bn_apply<BNL>(in[(size_t)(base+v)*CI+lane],sc[0],sh[0]);
            }
            unsigned long long a0[8];
            #pragma unroll
            for(int v=0;v<8;v++) a0[v]=bias0;
            #pragma unroll
            for(int ci=0;ci<CI;ci++){
                unsigned long long w=sW[ci*32+lane];
                #pragma unroll
                for(int v=0;v<8;v++)
                    a0[v]=ffma2(dup2(__shfl_sync(0xffffffffu,r[v],ci)),w,a0[v]);
            }
            #pragma unroll
            for(int v=0;v<8;v++) if(val[v]){
                float2 o; upk2(a0[v],o.x,o.y);
                *(float2*)&out[(size_t)(base+v)*CO+lane*2]=o;
            }
        }
    } else {
        __shared__ float Ws[CI*CO];
        for(int i=threadIdx.x;i<CI*CO;i+=blockDim.x) Ws[i]=W[13*CI*CO+i];
        __syncthreads();
        float bs=bias[lane];
        int base0=(((blockIdx.x*blockDim.x+threadIdx.x)>>5)<<2);
        int stride4=((gridDim.x*blockDim.x)>>5)<<2;
        for(int base=base0;base<TOT;base+=stride4){
            bool val[4];
            float r[4];
            #pragma unroll
            for(int v=0;v<4;v++){
                val[v]=(d_unq[base+v]<SENTV);
                r[v]=(lane<CI)?bn_apply<BNL>(in[(size_t)(base+v)*CI+lane],sc[0],sh[0]):0.f;
            }
            float acc[4]={bs,bs,bs,bs};
            #pragma unroll
            for(int ci=0;ci<CI;ci++){
                float w=Ws[ci*CO+lane];
                #pragma unroll
                for(int v=0;v<4;v++)
                    acc[v]+=__shfl_sync(0xffffffffu,r[v],ci)*w;
            }
            #pragma unroll
            for(int v=0;v<4;v++) if(val[v])
                out[(size_t)(base+v)*CO+lane]=acc[v];
        }
    }
}

// ---------- off-center scatter (V=8 pairs per warp for CO>=64, V=4 for CO=32) ----------
template<int CI,int CO,int BNL>
__global__ void k_scatter(const float* __restrict__ in, float* __restrict__ out,
        const float* __restrict__ W,
        const float* __restrict__ gam, const float* __restrict__ bet){
    constexpr int RI=(CI+31)/32;
    __shared__ int s_ko,s_base,s_cnt;
    int lane=threadIdx.x&31, warp=threadIdx.x>>5;
    int nwarps=blockDim.x>>5;
    const unsigned totc=d_totchunks;
    float sc[RI],sh[RI];
    bn_hoist<BNL,RI,CI>(lane,gam,bet,sc,sh);
    if constexpr (CO==128){
        __shared__ ulonglong2 sW[CI*32];
        for(unsigned chunk=blockIdx.x; chunk<totc; chunk+=gridDim.x){
            if(threadIdx.x==0){
                int ko=0;
                while(chunk>=d_chunkpfx[ko+1]) ko++;
                s_ko=ko;
                int base=(int)(chunk-d_chunkpfx[ko])*PPB;
                s_base=base;
                s_cnt=min(PPB,(int)d_paircnt[ko]-base);
            }
            __syncthreads();
            int ko=s_ko;
            for(int i=threadIdx.x;i<CI*32;i+=blockDim.x){
                int ci=i>>5, ln=i&31;
                float4 w=*(const float4*)&W[(size_t)ko*CI*CO+(size_t)ci*CO+ln*4];
                sW[i]=make_ulonglong2(pk2(w.x,w.y),pk2(w.z,w.w));
            }
            __syncthreads();
            int cnt=s_cnt, base=s_base;
            for(int p2=warp*8;p2<cnt;p2+=nwarps*8){
                int dst[8];
                float r[8][RI];
                #pragma unroll
                for(int v=0;v<8;v++){
                    int idx=min(p2+v,cnt-1);
                    unsigned long long pr=d_pairs[(size_t)ko*TOT+base+idx];
                    dst[v]=(int)(pr>>32);
                    int src=(int)(pr&0xFFFFFFFFu);
                    #pragma unroll
                    for(int j=0;j<RI;j++)
                        r[v][j]=bn_apply<BNL>(in[(size_t)src*CI+lane+32*j],sc[j],sh[j]);
                }
                unsigned long long a0[8]={0,0,0,0,0,0,0,0},a1[8]={0,0,0,0,0,0,0,0};
                #pragma unroll
                for(int ci=0;ci<CI;ci++){
                    ulonglong2 w=sW[ci*32+lane];
                    #pragma unroll
                    for(int v=0;v<8;v++){
                        unsigned long long ff=dup2(__shfl_sync(0xffffffffu,r[v][ci>>5],ci&31));
                        a0[v]=ffma2(ff,w.x,a0[v]);
                        a1[v]=ffma2(ff,w.y,a1[v]);
                    }
                }
                #pragma unroll
                for(int v=0;v<8;v++) if(p2+v<cnt){
                    float o0,o1,o2,o3;
                    upk2(a0[v],o0,o1); upk2(a1[v],o2,o3);
                    red4(&out[(size_t)dst[v]*CO+lane*4],o0,o1,o2,o3);
                }
            }
            __syncthreads();
        }
    } else if constexpr (CO==64){
        __shared__ unsigned long long sW[CI*32];
        for(unsigned chunk=blockIdx.x; chunk<totc; chunk+=gridDim.x){
            if(threadIdx.x==0){
                int ko=0;
                while(chunk>=d_chunkpfx[ko+1]) ko++;
                s_ko=ko;
                int base=(int)(chunk-d_chunkpfx[ko])*PPB;
                s_base=base;
                s_cnt=min(PPB,(int)d_paircnt[ko]-base);
            }
            __syncthreads();
            int ko=s_ko;
            for(int i=threadIdx.x;i<CI*32;i+=blockDim.x){
                int ci=i>>5, ln=i&31;
                float2 w=*(const float2*)&W[(size_t)ko*CI*CO+(size_t)ci*CO+ln*2];
                sW[i]=pk2(w.x,w.y);
            }
            __syncthreads();
            int cnt=s_cnt, base=s_base;
            for(int p2=warp*8;p2<cnt;p2+=nwarps*8){
                int dst[8];
                float r[8];
                #pragma unroll
                for(int v=0;v<8;v++){
                    int idx=min(p2+v,cnt-1);
                    unsigned long long pr=d_pairs[(size_t)ko*TOT+base+idx];
                    dst[v]=(int)(pr>>32);
                    int src=(int)(pr&0xFFFFFFFFu);
                    r[v]=bn_apply<BNL>(in[(size_t)src*CI+lane],sc[0],sh[0]);
                }
                unsigned long long a0[8]={0,0,0,0,0,0,0,0};
                #pragma unroll
                for(int ci=0;ci<CI;ci++){
                    unsigned long long w=sW[ci*32+lane];
                    #pragma unroll
                    for(int v=0;v<8;v++)
                        a0[v]=ffma2(dup2(__shfl_sync(0xffffffffu,r[v],ci)),w,a0[v]);
                }
                #pragma unroll
                for(int v=0;v<8;v++) if(p2+v<cnt){
                    float o0,o1; upk2(a0[v],o0,o1);
                    red2(&out[(size_t)dst[v]*CO+lane*2],o0,o1);
                }
            }
            __syncthreads();
        }
    } else {
        __shared__ float Ws[CI*CO];
        for(unsigned chunk=blockIdx.x; chunk<totc; chunk+=gridDim.x){
            if(threadIdx.x==0){
                int ko=0;
                while(chunk>=d_chunkpfx[ko+1]) ko++;
                s_ko=ko;
                int base=(int)(chunk-d_chunkpfx[ko])*PPB;
                s_base=base;
                s_cnt=min(PPB,(int)d_paircnt[ko]-base);
            }
            __syncthreads();
            int ko=s_ko;
            for(int i=threadIdx.x;i<CI*CO;i+=blockDim.x) Ws[i]=W[(size_t)ko*CI*CO+i];
            __syncthreads();
            int cnt=s_cnt, base=s_base;
            for(int p2=warp*4;p2<cnt;p2+=nwarps*4){
                int dst[4];
                float r[4];
                #pragma unroll
                for(int v=0;v<4;v++){
                    int idx=min(p2+v,cnt-1);
                    unsigned long long pr=d_pairs[(size_t)ko*TOT+base+idx];
                    dst[v]=(int)(pr>>32);
                    int src=(int)(pr&0xFFFFFFFFu);
                    r[v]=(lane<CI)?bn_apply<BNL>(in[(size_t)src*CI+lane],sc[0],sh[0]):0.f;
                }
                float acc[4]={0,0,0,0};
                #pragma unroll
                for(int ci=0;ci<CI;ci++){
                    float w=Ws[ci*CO+lane];
                    #pragma unroll
                    for(int v=0;v<4;v++)
                        acc[v]+=__shfl_sync(0xffffffffu,r[v],ci)*w;
                }
                #pragma unroll
                for(int v=0;v<4;v++) if(p2+v<cnt)
                    atomicAdd(&out[(size_t)dst[v]*CO+lane],acc[v]);
            }
            __syncthreads();
        }
    }
}

// ---------- BN stats ----------
template<int CO>
__global__ void k_stats(const float* __restrict__ h, int L){
    constexpr int TPS=CO/4;
    constexpr int SUBS=128/TPS;
    int tid=threadIdx.x;
    int q=tid%TPS;
    int sub=tid/TPS;
    float s0=0,s1=0,s2=0,s3=0,t0=0,t1=0,t2=0,t3=0;
    for(int slot=blockIdx.x*SUBS+sub; slot<TOT; slot+=gridDim.x*SUBS){
        if(d_unq[slot]<SENTV){
            float4 v=*(const float4*)&h[(size_t)slot*CO+q*4];
            s0+=v.x; s1+=v.y; s2+=v.z; s3+=v.w;
            t0+=v.x*v.x; t1+=v.y*v.y; t2+=v.z*v.z; t3+=v.w*v.w;
        }
    }
    __shared__ float ss[128][8];
    ss[tid][0]=s0; ss[tid][1]=s1; ss[tid][2]=s2; ss[tid][3]=s3;
    ss[tid][4]=t0; ss[tid][5]=t1; ss[tid][6]=t2; ss[tid][7]=t3;
    __syncthreads();
    if(sub==0){
        #pragma unroll 4
        for(int k=1;k<SUBS;k++){
            s0+=ss[k*TPS+q][0]; s1+=ss[k*TPS+q][1]; s2+=ss[k*TPS+q][2]; s3+=ss[k*TPS+q][3];
            t0+=ss[k*TPS+q][4]; t1+=ss[k*TPS+q][5]; t2+=ss[k*TPS+q][6]; t3+=ss[k*TPS+q][7];
        }
        int c=q*4;
        atomicAdd(&d_sumv[L][c+0],(double)s0);
        atomicAdd(&d_sumv[L][c+1],(double)s1);
        atomicAdd(&d_sumv[L][c+2],(double)s2);
        atomicAdd(&d_sumv[L][c+3],(double)s3);
        atomicAdd(&d_sumsq[L][c+0],(double)t0);
        atomicAdd(&d_sumsq[L][c+1],(double)t1);
        atomicAdd(&d_sumsq[L][c+2],(double)t2);
        atomicAdd(&d_sumsq[L][c+3],(double)t3);
    }
}

__global__ void k_bnfinal(int L,int CO){
    int c=threadIdx.x;
    if(c<CO){
        double n=(double)max(d_validcount,1);
        double m=d_sumv[L][c]/n;
        double var=d_sumsq[L][c]/n-m*m;
        if(var<0.0) var=0.0;
        d_bnmean[L][c]=(float)m;
        d_bnrstd[L][c]=rsqrtf((float)var+1e-5f);
    }
}

__global__ void k_out(const float* __restrict__ mask, float* __restrict__ out,
                      const float* __restrict__ gam, const float* __restrict__ bet){
    int stride=gridDim.x*blockDim.x;
    int q0=blockIdx.x*blockDim.x+threadIdx.x;
    int c4=(q0&31)*4;
    float a0=d_bnrstd[2][c4+0]*gam[c4+0], b0=bet[c4+0]-d_bnmean[2][c4+0]*a0;
    float a1=d_bnrstd[2][c4+1]*gam[c4+1], b1=bet[c4+1]-d_bnmean[2][c4+1]*a1;
    float a2=d_bnrstd[2][c4+2]*gam[c4+2], b2=bet[c4+2]-d_bnmean[2][c4+2]*a2;
    float a3=d_bnrstd[2][c4+3]*gam[c4+3], b3=bet[c4+3]-d_bnmean[2][c4+3]*a3;
    for(int q=q0; q<TOT*32; q+=stride){
        int g=q>>5;
        int slot=((g>>16)<<16)+d_invmap[g];
        float4 v=*(const float4*)&d_h3[(size_t)slot*128+c4];
        float m=mask[g];
        float4 o;
        o.x=fmaxf(fmaf(v.x,a0,b0),0.f)*m;
        o.y=fmaxf(fmaf(v.y,a1,b1),0.f)*m;
        o.z=fmaxf(fmaf(v.z,a2,b2),0.f)*m;
        o.w=fmaxf(fmaf(v.w,a3,b3),0.f)*m;
        *(float4*)&out[(size_t)q*4]=o;
    }
}

extern "C" void kernel_launch(void* const* d_in, const int* in_sizes, int n_in,
                              void* d_out, int out_size) {
    const float* xyz =(const float*)d_in[0];
    const float* feat=(const float*)d_in[1];
    const float* mask=(const float*)d_in[2];
    const float* W1=(const float*)d_in[3];
    const float* b1=(const float*)d_in[4];
    const float* g1=(const float*)d_in[5];
    const float* be1=(const float*)d_in[6];
    const float* W2=(const float*)d_in[7];
    const float* b2=(const float*)d_in[8];
    const float* g2=(const float*)d_in[9];
    const float* be2=(const float*)d_in[10];
    const float* W3=(const float*)d_in[11];
    const float* b3=(const float*)d_in[12];
    const float* g3=(const float*)d_in[13];
    const float* be3=(const float*)d_in[14];
    float* out=(float*)d_out;

    void *p_h1,*p_h2,*p_h3,*p_vf;
    cudaGetSymbolAddress(&p_h1,d_h1);
    cudaGetSymbolAddress(&p_h2,d_h2);
    cudaGetSymbolAddress(&p_h3,d_h3);
    cudaGetSymbolAddress(&p_vf,d_vfeat);
    float* h1=(float*)p_h1; float* h2=(float*)p_h2; float* h3=(float*)p_h3;
    float* vf=(float*)p_vf;

    k_init<<<1024,256>>>();
    k_min<<<256,256>>>(xyz);
    k_mark<<<1024,256>>>(xyz);
    k_scanA<<<NBLKTOT,256>>>();
    k_scanB<<<1,32>>>();
    k_scanC<<<NBLKTOT,256>>>();
    k_build2<<<2048,256>>>(feat,mask);
    k_vdiv<<<1024,256>>>();
    k_pairs<<<2048,256>>>();
    k_sched<<<1,1>>>();

    // Layer 1: 16 -> 32
    k_center<CIN,32,-1><<<2048,256>>>(vf,h1,W1,b1,nullptr,nullptr);
    k_scatter<CIN,32,-1><<<2048,256>>>(vf,h1,W1,nullptr,nullptr);
    k_stats<32><<<2048,128>>>(h1,0);
    k_bnfinal<<<1,128>>>(0,32);
    // Layer 2: 32 -> 64 (fuses BN0+relu on input)
    k_center<32,64,0><<<2048,256>>>(h1,h2,W2,b2,g1,be1);
    k_scatter<32,64,0><<<2048,256>>>(h1,h2,W2,g1,be1);
    k_stats<64><<<2048,128>>>(h2,1);
    k_bnfinal<<<1,128>>>(1,64);
    // Layer 3: 64 -> 128 (fuses BN1+relu on input)
    k_center<64,128,1><<<2048,256>>>(h2,h3,W3,b3,g2,be2);
    k_scatter<64,128,1><<<2048,256>>>(h2,h3,W3,g2,be2);
    k_stats<128><<<2048,128>>>(h3,2);
    k_bnfinal<<<1,128>>>(2,128);
    // Final: BN2+relu + gather by inv + mask
    k_out<<<8192,256>>>(mask,out,g3,be3);
    // Restore LUT/presence to zeros for next replay
    k_unclear<<<1024,256>>>();
}